// round 10
// baseline (speedup 1.0000x reference)
#include <cuda_runtime.h>
#include <cstdint>
#include <math.h>

#define NN 50000
#define EE 800000
#define NE 850000      // EE + NN self loops
#define D1 256         // H*DH = H*DOUT paths both 256 wide

#define SCAN_CH 256
#define SCAN_NB ((NN + SCAN_CH - 1) / SCAN_CH)   // 196

// ---------------- scratch (device globals; no allocation allowed) ----------
__device__ int   g_is64;
__device__ int   g_src[NE];     // edge order
__device__ int   g_dst[NE];
__device__ int   g_srcp[NE];    // CSR (dst-grouped) order
__device__ int   g_deg[NN];
__device__ int   g_off[NN + 1];
__device__ int   g_cur[NN];
__device__ int   g_bsum[SCAN_NB];
__device__ float g_xl[(size_t)NN * D1];
__device__ float g_xr[(size_t)NN * D1];
__device__ float g_h [(size_t)NN * D1];

// host-side side stream + events, created once at load (no device memory)
struct AuxStreams {
    cudaStream_t s2;
    cudaEvent_t  e_fork, e_join;
    AuxStreams() {
        cudaStreamCreateWithFlags(&s2, cudaStreamNonBlocking);
        cudaEventCreateWithFlags(&e_fork, cudaEventDisableTiming);
        cudaEventCreateWithFlags(&e_join, cudaEventDisableTiming);
    }
};
static AuxStreams g_aux;

// ---------------- detect dtype (block 0) + zero degree array ---------------
__global__ void k_detect_zero(const unsigned* __restrict__ p) {
    int i = blockIdx.x * blockDim.x + threadIdx.x;
    if (i < NN) g_deg[i] = 0;
    if (blockIdx.x == 0) {
        __shared__ unsigned acc;
        if (threadIdx.x == 0) acc = 0u;
        __syncthreads();
        if (threadIdx.x < 128) {
            unsigned v = p[threadIdx.x * 2 + 1];
            if (v) atomicOr(&acc, 1u);
        }
        __syncthreads();
        if (threadIdx.x == 0) g_is64 = (acc == 0u) ? 1 : 0;
    }
}

// ---------------- build src/dst with self loops + degree count -------------
__global__ void k_build_count(const void* __restrict__ ei) {
    int i = blockIdx.x * blockDim.x + threadIdx.x;
    if (i >= NE) return;
    int s, d;
    if (i < EE) {
        if (g_is64) {
            const long long* p = (const long long*)ei;
            s = (int)p[i];
            d = (int)p[EE + i];
        } else {
            const int* p = (const int*)ei;
            s = p[i];
            d = p[EE + i];
        }
    } else {
        s = d = i - EE;
    }
    g_src[i] = s;
    g_dst[i] = d;
    atomicAdd(&g_deg[d], 1);
}

// ---------------- 3-phase multi-block exclusive scan -----------------------
__global__ void k_scan1() {
    __shared__ int sm[SCAN_CH];
    int b = blockIdx.x, t = threadIdx.x;
    int i = b * SCAN_CH + t;
    int v = (i < NN) ? g_deg[i] : 0;
    sm[t] = v;
    __syncthreads();
#pragma unroll
    for (int off = 1; off < SCAN_CH; off <<= 1) {
        int u = (t >= off) ? sm[t - off] : 0;
        __syncthreads();
        sm[t] += u;
        __syncthreads();
    }
    if (i < NN) g_off[i] = sm[t] - v;           // exclusive within block
    if (t == SCAN_CH - 1) g_bsum[b] = sm[t];    // block total
}

__global__ void k_scan2() {
    __shared__ int sm[256];
    int t = threadIdx.x;
    int v = (t < SCAN_NB) ? g_bsum[t] : 0;
    sm[t] = v;
    __syncthreads();
#pragma unroll
    for (int off = 1; off < 256; off <<= 1) {
        int u = (t >= off) ? sm[t - off] : 0;
        __syncthreads();
        sm[t] += u;
        __syncthreads();
    }
    if (t < SCAN_NB) g_bsum[t] = sm[t] - v;     // exclusive block offsets
    if (t == 255) g_off[NN] = sm[255];          // grand total (== NE)
}

__global__ void k_scan3() {
    int i = blockIdx.x * blockDim.x + threadIdx.x;
    if (i >= NN) return;
    int o = g_off[i] + g_bsum[i >> 8];          // SCAN_CH == 256
    g_off[i] = o;
    g_cur[i] = o;
}

__global__ void k_scatter() {
    int i = blockIdx.x * blockDim.x + threadIdx.x;
    if (i >= NE) return;
    int p = atomicAdd(&g_cur[g_dst[i]], 1);
    g_srcp[p] = g_src[i];
}

// ---------------- tf32 tensor-core GEMM, double-buffered, 2 CTA/SM ---------
__device__ __forceinline__ unsigned f2tf32(float x) {
    unsigned r;
    asm("cvt.rna.tf32.f32 %0, %1;" : "=r"(r) : "f"(x));
    return r;
}
__device__ __forceinline__ void mma_tf32(float* c, unsigned a0, unsigned a1,
                                         unsigned a2, unsigned a3,
                                         unsigned b0, unsigned b1) {
    asm volatile(
        "mma.sync.aligned.m16n8k8.row.col.f32.tf32.tf32.f32 "
        "{%0,%1,%2,%3}, {%4,%5,%6,%7}, {%8,%9}, {%0,%1,%2,%3};"
        : "+f"(c[0]), "+f"(c[1]), "+f"(c[2]), "+f"(c[3])
        : "r"(a0), "r"(a1), "r"(a2), "r"(a3), "r"(b0), "r"(b1));
}

__global__ __launch_bounds__(256, 2)
void k_gemm(const float* __restrict__ A,
            const float* __restrict__ W0, const float* __restrict__ W1,
            float* __restrict__ C0, float* __restrict__ C1,
            int N, int M, int Kc) {
    __shared__ unsigned As[2][16][132];   // [buf][k][m] padded
    __shared__ unsigned Bs[2][16][132];   // [buf][k][n]
    const int t = threadIdx.x;
    const int lane = t & 31, warp = t >> 5;
    const int wm = (warp >> 2) << 6;   // 0 / 64
    const int wn = (warp & 3) << 5;    // 0..96
    const int row0 = blockIdx.x * 128;
    int col0 = blockIdx.y * 128;
    const float* W = W0;
    float* C = C0;
    if (col0 >= Kc) { col0 -= Kc; W = W1; C = C1; }

    float acc[4][4][4];
#pragma unroll
    for (int mt = 0; mt < 4; mt++)
#pragma unroll
        for (int nt = 0; nt < 4; nt++)
#pragma unroll
            for (int j = 0; j < 4; j++) acc[mt][nt][j] = 0.f;

    const int arow = t >> 1;             // 0..127
    const int ak   = (t & 1) * 8;        // 0 / 8 float offset in chunk
    const int brow = t >> 4;             // 0..15 (k)
    const int bcol = (t & 15) * 4;       // n offset; second float4 at +64
    const bool aok = (row0 + arow) < N;

    float4 aR[2], bR[2];
    {   // chunk 0: load + store to buffer 0
        const float* ap = A + (size_t)(row0 + arow) * M + ak;
#pragma unroll
        for (int q = 0; q < 2; q++)
            aR[q] = aok ? *(const float4*)(ap + q * 4)
                        : make_float4(0.f, 0.f, 0.f, 0.f);
        const float* bp = W + (size_t)brow * Kc + col0 + bcol;
#pragma unroll
        for (int q = 0; q < 2; q++)
            bR[q] = *(const float4*)(bp + q * 64);
#pragma unroll
        for (int q = 0; q < 2; q++) {
            int k = ak + q * 4;
            As[0][k + 0][arow] = f2tf32(aR[q].x);
            As[0][k + 1][arow] = f2tf32(aR[q].y);
            As[0][k + 2][arow] = f2tf32(aR[q].z);
            As[0][k + 3][arow] = f2tf32(aR[q].w);
        }
#pragma unroll
        for (int q = 0; q < 2; q++) {
            int nb = bcol + q * 64;
            Bs[0][brow][nb + 0] = f2tf32(bR[q].x);
            Bs[0][brow][nb + 1] = f2tf32(bR[q].y);
            Bs[0][brow][nb + 2] = f2tf32(bR[q].z);
            Bs[0][brow][nb + 3] = f2tf32(bR[q].w);
        }
    }
    __syncthreads();

    const int nchunk = M >> 4;
    const int r = lane >> 2, c = lane & 3;
    for (int ch = 0; ch < nchunk; ch++) {
        int p = ch & 1;
        bool more = (ch + 1 < nchunk);
        if (more) {                      // issue next chunk's global loads now
            int k0 = (ch + 1) << 4;
            const float* ap = A + (size_t)(row0 + arow) * M + k0 + ak;
#pragma unroll
            for (int q = 0; q < 2; q++)
                aR[q] = aok ? *(const float4*)(ap + q * 4)
                            : make_float4(0.f, 0.f, 0.f, 0.f);
            const float* bp = W + (size_t)(k0 + brow) * Kc + col0 + bcol;
#pragma unroll
            for (int q = 0; q < 2; q++)
                bR[q] = *(const float4*)(bp + q * 64);
        }
        // compute from buffer p (hides the global load latency above)
#pragma unroll
        for (int ks = 0; ks < 2; ks++) {
            int k = ks * 8;
            unsigned a[4][4], b[4][2];
#pragma unroll
            for (int mt = 0; mt < 4; mt++) {
                int mb = wm + mt * 16 + r;
                a[mt][0] = As[p][k + c][mb];
                a[mt][1] = As[p][k + c][mb + 8];
                a[mt][2] = As[p][k + c + 4][mb];
                a[mt][3] = As[p][k + c + 4][mb + 8];
            }
#pragma unroll
            for (int nt = 0; nt < 4; nt++) {
                int nb = wn + nt * 8 + r;
                b[nt][0] = Bs[p][k + c][nb];
                b[nt][1] = Bs[p][k + c + 4][nb];
            }
#pragma unroll
            for (int mt = 0; mt < 4; mt++)
#pragma unroll
                for (int nt = 0; nt < 4; nt++)
                    mma_tf32(acc[mt][nt], a[mt][0], a[mt][1], a[mt][2],
                             a[mt][3], b[nt][0], b[nt][1]);
        }
        if (more) {                      // store next chunk to other buffer
            int np = p ^ 1;
#pragma unroll
            for (int q = 0; q < 2; q++) {
                int k = ak + q * 4;
                As[np][k + 0][arow] = f2tf32(aR[q].x);
                As[np][k + 1][arow] = f2tf32(aR[q].y);
                As[np][k + 2][arow] = f2tf32(aR[q].z);
                As[np][k + 3][arow] = f2tf32(aR[q].w);
            }
#pragma unroll
            for (int q = 0; q < 2; q++) {
                int nb = bcol + q * 64;
                Bs[np][brow][nb + 0] = f2tf32(bR[q].x);
                Bs[np][brow][nb + 1] = f2tf32(bR[q].y);
                Bs[np][brow][nb + 2] = f2tf32(bR[q].z);
                Bs[np][brow][nb + 3] = f2tf32(bR[q].w);
            }
            __syncthreads();
        }
    }
    // epilogue
    const int c2 = (lane & 3) * 2;
#pragma unroll
    for (int mt = 0; mt < 4; mt++) {
#pragma unroll
        for (int half = 0; half < 2; half++) {
            int row = row0 + wm + mt * 16 + r + half * 8;
            if (row < N) {
#pragma unroll
                for (int nt = 0; nt < 4; nt++) {
                    float2 v = half
                        ? make_float2(acc[mt][nt][2], acc[mt][nt][3])
                        : make_float2(acc[mt][nt][0], acc[mt][nt][1]);
                    *(float2*)(C + (size_t)row * Kc + col0 + wn + nt * 8 + c2) = v;
                }
            }
        }
    }
}

// ---------------- fused GATv2 edge pass: pairwise online softmax -----------
// One warp per dst node. Lane l owns dims [4l..4l+3] (head hA=l>>3) in float4
// A and dims [128+4l..128+4l+3] (head hA+4) in float4 B. Edges processed two
// at a time: the two SHFL-reduce chains interleave (ILP 2), one joint softmax
// rescale per pair, pair-level load prefetch.
// MODE 0: bias+ELU, write 256-wide h. MODE 1: head-mean + bias, 32-wide out.
template<int MODE>
__global__ void k_fused(const float* __restrict__ xl, const float* __restrict__ xr,
                        const float* __restrict__ att, const float* __restrict__ bias,
                        float* __restrict__ out) {
    int n = (blockIdx.x * blockDim.x + threadIdx.x) >> 5;
    int lane = threadIdx.x & 31;
    if (n >= NN) return;
    int beg = g_off[n], end = g_off[n + 1];

    // per-dst target transform + attention vector slices (register resident)
    const float4* xrp = (const float4*)(xr + (size_t)n * D1);
    float4 r0 = xrp[lane], r1 = xrp[32 + lane];
    float4 atA = *(const float4*)(att + 4 * lane);
    float4 atB = *(const float4*)(att + 128 + 4 * lane);

    float mA = -1e30f, mB = -1e30f, sA = 0.f, sB = 0.f;
    float4 acc0 = make_float4(0.f, 0.f, 0.f, 0.f);
    float4 acc1 = make_float4(0.f, 0.f, 0.f, 0.f);

    // prologue: load first pair (self-loop guarantees beg < end)
    int i = beg;
    int sa = __ldg(&g_srcp[i]);
    int sb = (i + 1 < end) ? __ldg(&g_srcp[i + 1]) : sa;
    const float4* pa = (const float4*)(xl + (size_t)sa * D1);
    const float4* pb = (const float4*)(xl + (size_t)sb * D1);
    float4 c0a = pa[lane], c1a = pa[32 + lane];   // edge i
    float4 c0b = pb[lane], c1b = pb[32 + lane];   // edge i+1

    for (; i + 1 < end; i += 2) {
        float4 e0a = c0a, e1a = c1a, e0b = c0b, e1b = c1b;
        int j = i + 2;
        if (j < end) {                   // prefetch next pair
            int na = __ldg(&g_srcp[j]);
            int nb = (j + 1 < end) ? __ldg(&g_srcp[j + 1]) : na;
            const float4* qa = (const float4*)(xl + (size_t)na * D1);
            const float4* qb = (const float4*)(xl + (size_t)nb * D1);
            c0a = qa[lane]; c1a = qa[32 + lane];
            c0b = qb[lane]; c1b = qb[32 + lane];
        }
        // logits for both edges (independent chains -> ILP)
        float z, cA1, cB1, cA2, cB2;
        z = e0a.x + r0.x; z = z > 0.f ? z : 0.2f * z; cA1  = z * atA.x;
        z = e0a.y + r0.y; z = z > 0.f ? z : 0.2f * z; cA1 += z * atA.y;
        z = e0a.z + r0.z; z = z > 0.f ? z : 0.2f * z; cA1 += z * atA.z;
        z = e0a.w + r0.w; z = z > 0.f ? z : 0.2f * z; cA1 += z * atA.w;
        z = e1a.x + r1.x; z = z > 0.f ? z : 0.2f * z; cB1  = z * atB.x;
        z = e1a.y + r1.y; z = z > 0.f ? z : 0.2f * z; cB1 += z * atB.y;
        z = e1a.z + r1.z; z = z > 0.f ? z : 0.2f * z; cB1 += z * atB.z;
        z = e1a.w + r1.w; z = z > 0.f ? z : 0.2f * z; cB1 += z * atB.w;
        z = e0b.x + r0.x; z = z > 0.f ? z : 0.2f * z; cA2  = z * atA.x;
        z = e0b.y + r0.y; z = z > 0.f ? z : 0.2f * z; cA2 += z * atA.y;
        z = e0b.z + r0.z; z = z > 0.f ? z : 0.2f * z; cA2 += z * atA.z;
        z = e0b.w + r0.w; z = z > 0.f ? z : 0.2f * z; cA2 += z * atA.w;
        z = e1b.x + r1.x; z = z > 0.f ? z : 0.2f * z; cB2  = z * atB.x;
        z = e1b.y + r1.y; z = z > 0.f ? z : 0.2f * z; cB2 += z * atB.y;
        z = e1b.z + r1.z; z = z > 0.f ? z : 0.2f * z; cB2 += z * atB.z;
        z = e1b.w + r1.w; z = z > 0.f ? z : 0.2f * z; cB2 += z * atB.w;
#pragma unroll
        for (int off = 1; off < 8; off <<= 1) {
            cA1 += __shfl_xor_sync(0xffffffffu, cA1, off);
            cA2 += __shfl_xor_sync(0xffffffffu, cA2, off);
            cB1 += __shfl_xor_sync(0xffffffffu, cB1, off);
            cB2 += __shfl_xor_sync(0xffffffffu, cB2, off);
        }
        // joint online softmax update: one rescale per pair (head A)
        float mAn = fmaxf(mA, fmaxf(cA1, cA2));
        float scA = __expf(mA - mAn);
        float p1  = __expf(cA1 - mAn);
        float p2  = __expf(cA2 - mAn);
        sA = sA * scA + p1 + p2;
        acc0.x = acc0.x * scA + p1 * e0a.x + p2 * e0b.x;
        acc0.y = acc0.y * scA + p1 * e0a.y + p2 * e0b.y;
        acc0.z = acc0.z * scA + p1 * e0a.z + p2 * e0b.z;
        acc0.w = acc0.w * scA + p1 * e0a.w + p2 * e0b.w;
        mA = mAn;
        // head B
        float mBn = fmaxf(mB, fmaxf(cB1, cB2));
        float scB = __expf(mB - mBn);
        float q1  = __expf(cB1 - mBn);
        float q2  = __expf(cB2 - mBn);
        sB = sB * scB + q1 + q2;
        acc1.x = acc1.x * scB + q1 * e1a.x + q2 * e1b.x;
        acc1.y = acc1.y * scB + q1 * e1a.y + q2 * e1b.y;
        acc1.z = acc1.z * scB + q1 * e1a.z + q2 * e1b.z;
        acc1.w = acc1.w * scB + q1 * e1a.w + q2 * e1b.w;
        mB = mBn;
    }
    if (i < end) {                       // odd tail: edge row is in c0a/c1a
        float z, cA, cB;
        z = c0a.x + r0.x; z = z > 0.f ? z : 0.2f * z; cA  = z * atA.x;
        z = c0a.y + r0.y; z = z > 0.f ? z : 0.2f * z; cA += z * atA.y;
        z = c0a.z + r0.z; z = z > 0.f ? z : 0.2f * z; cA += z * atA.z;
        z = c0a.w + r0.w; z = z > 0.f ? z : 0.2f * z; cA += z * atA.w;
        z = c1a.x + r1.x; z = z > 0.f ? z : 0.2f * z; cB  = z * atB.x;
        z = c1a.y + r1.y; z = z > 0.f ? z : 0.2f * z; cB += z * atB.y;
        z = c1a.z + r1.z; z = z > 0.f ? z : 0.2f * z; cB += z * atB.z;
        z = c1a.w + r1.w; z = z > 0.f ? z : 0.2f * z; cB += z * atB.w;
#pragma unroll
        for (int off = 1; off < 8; off <<= 1) {
            cA += __shfl_xor_sync(0xffffffffu, cA, off);
            cB += __shfl_xor_sync(0xffffffffu, cB, off);
        }
        float mAn = fmaxf(mA, cA);
        float scA = __expf(mA - mAn);
        float pA  = __expf(cA - mAn);
        sA = sA * scA + pA;
        acc0.x = acc0.x * scA + pA * c0a.x;
        acc0.y = acc0.y * scA + pA * c0a.y;
        acc0.z = acc0.z * scA + pA * c0a.z;
        acc0.w = acc0.w * scA + pA * c0a.w;
        mA = mAn;
        float mBn = fmaxf(mB, cB);
        float scB = __expf(mB - mBn);
        float pB  = __expf(cB - mBn);
        sB = sB * scB + pB;
        acc1.x = acc1.x * scB + pB * c1a.x;
        acc1.y = acc1.y * scB + pB * c1a.y;
        acc1.z = acc1.z * scB + pB * c1a.z;
        acc1.w = acc1.w * scB + pB * c1a.w;
        mB = mBn;
    }
    float iA = 1.f / (sA + 1e-16f);
    float iB = 1.f / (sB + 1e-16f);
    acc0.x *= iA; acc0.y *= iA; acc0.z *= iA; acc0.w *= iA;
    acc1.x *= iB; acc1.y *= iB; acc1.z *= iB; acc1.w *= iB;

    if (MODE == 1) {
        // head-mean: both float4s map to output cols 4*(lane&7)..+3; sum
        // heads across lanes {l, l^8, l^16, l^24}
        float4 tv = make_float4(acc0.x + acc1.x, acc0.y + acc1.y,
                                acc0.z + acc1.z, acc0.w + acc1.w);
#pragma unroll
        for (int off = 8; off <= 16; off <<= 1) {
            tv.x += __shfl_xor_sync(0xffffffffu, tv.x, off);
            tv.y += __shfl_xor_sync(0xffffffffu, tv.y, off);
            tv.z += __shfl_xor_sync(0xffffffffu, tv.z, off);
            tv.w += __shfl_xor_sync(0xffffffffu, tv.w, off);
        }
        if (lane < 8) {
            float4 bb = *(const float4*)(bias + lane * 4);
            float4 r = make_float4(tv.x * 0.125f + bb.x, tv.y * 0.125f + bb.y,
                                   tv.z * 0.125f + bb.z, tv.w * 0.125f + bb.w);
            *(float4*)(out + (size_t)n * 32 + lane * 4) = r;
        }
    } else {
        // fused bias + ELU for layer 1 hidden state
        float4 b0 = *(const float4*)(bias + lane * 4);
        float4 b1 = *(const float4*)(bias + 128 + lane * 4);
        float4 w0, w1;
        float v;
        v = acc0.x + b0.x; w0.x = v > 0.f ? v : expm1f(v);
        v = acc0.y + b0.y; w0.y = v > 0.f ? v : expm1f(v);
        v = acc0.z + b0.z; w0.z = v > 0.f ? v : expm1f(v);
        v = acc0.w + b0.w; w0.w = v > 0.f ? v : expm1f(v);
        v = acc1.x + b1.x; w1.x = v > 0.f ? v : expm1f(v);
        v = acc1.y + b1.y; w1.y = v > 0.f ? v : expm1f(v);
        v = acc1.z + b1.z; w1.z = v > 0.f ? v : expm1f(v);
        v = acc1.w + b1.w; w1.w = v > 0.f ? v : expm1f(v);
        float4* op = (float4*)(out + (size_t)n * D1);
        op[lane] = w0;
        op[32 + lane] = w1;
    }
}

// ---------------- launch ---------------------------------------------------
extern "C" void kernel_launch(void* const* d_in, const int* in_sizes, int n_in,
                              void* d_out, int out_size) {
    const float* x    = (const float*)d_in[0];
    const void*  ei   = d_in[1];
    const float* Wl1  = (const float*)d_in[2];
    const float* Wr1  = (const float*)d_in[3];
    const float* att1 = (const float*)d_in[4];
    const float* b1   = (const float*)d_in[5];
    const float* Wl2  = (const float*)d_in[6];
    const float* Wr2  = (const float*)d_in[7];
    const float* att2 = (const float*)d_in[8];
    const float* b2   = (const float*)d_in[9];

    float *pxl, *pxr, *ph;
    cudaGetSymbolAddress((void**)&pxl, g_xl);
    cudaGetSymbolAddress((void**)&pxr, g_xr);
    cudaGetSymbolAddress((void**)&ph,  g_h);

    dim3 gg((NN + 127) / 128, 2 * D1 / 128);   // both Wl and Wr outputs
    const int ab = (NN * 32 + 255) / 256;      // warp per dst

    // fork: layer-1 GEMM (depends only on x/Wl1/Wr1) runs on side stream,
    // concurrent with the graph-prep chain on the main stream.
    cudaEventRecord(g_aux.e_fork, 0);
    cudaStreamWaitEvent(g_aux.s2, g_aux.e_fork, 0);
    k_gemm<<<gg, 256, 0, g_aux.s2>>>(x, Wl1, Wr1, pxl, pxr, NN, 128, D1);
    cudaEventRecord(g_aux.e_join, g_aux.s2);

    // graph prep (main stream, overlapped with GEMM1)
    k_detect_zero<<<(NN + 255) / 256, 256>>>((const unsigned*)ei);
    k_build_count<<<(NE + 255) / 256, 256>>>(ei);
    k_scan1<<<SCAN_NB, SCAN_CH>>>();
    k_scan2<<<1, 256>>>();
    k_scan3<<<(NN + 255) / 256, 256>>>();
    k_scatter<<<(NE + 255) / 256, 256>>>();

    // join: fused layer 1 needs both GEMM1 outputs and the CSR
    cudaStreamWaitEvent(0, g_aux.e_join, 0);
    k_fused<0><<<ab, 256>>>(pxl, pxr, att1, b1, ph);

    // layer 2 (serial dependence)
    k_gemm<<<gg, 256>>>(ph, Wl2, Wr2, pxl, pxr, NN, 256, D1);
    k_fused<1><<<ab, 256>>>(pxl, pxr, att2, b2, (float*)d_out);
}